// round 10
// baseline (speedup 1.0000x reference)
#include <cuda_runtime.h>
#include <cstdint>

typedef unsigned long long ull;

#define MAXN (1 << 21)

// g_nodes[i] packs {p : lo 32, sum : hi 32} in one 8B word. Final state:
// p == N, hi = full path sum. Gather reads the hi word.
__device__ ull g_nodes[MAXN];

__device__ __forceinline__ ull pack_node(unsigned p, float t) {
    return ((ull)__float_as_uint(t) << 32) | (ull)p;
}
__device__ __forceinline__ void st_cg(ull* a, ull v) {
    asm volatile("st.relaxed.gpu.b64 [%0], %1;" :: "l"(a), "l"(v) : "memory");
}

__device__ __forceinline__ float node_score(const float* f, const float* w, float b)
{
    float z = b;
    z += w[0] * f[0] + w[1] * f[1] + w[2] * f[2] + w[3] * f[3] + w[4] * f[4];
    #pragma unroll
    for (int j = 6; j < 15; j++)
        z += w[j - 1] * __logf(fabsf(f[j]) + 1e-10f);
    z += w[14] * (sqrtf(f[7]) / (sqrtf(f[6]) + 1e-10f));
    float sn, cs;
    __sincosf(f[5], &sn, &cs);
    z += w[15] * cs + w[16] * sn;
    return 1.0f / (1.0f + __expf(-z));
}

// ---------------------------------------------------------------------------
// Combined kernel: blocks [0, p1_blocks) run phase1 on [p1_base, p1_end)
// (768 nodes/block, SMEM-staged attr stream -> DRAM-bound); the remaining
// blocks resolve slab [rs_start, rs_end) (1 thread/node pointer chase ->
// latency-bound, fills idle issue/l1tex slots under phase1's streaming).
// Resolve invariant: all of g_nodes[0, rs_end) was written by PRIOR kernels;
// nodes < rs_start are final. parent[i] < i => termination; racy in-slab
// reads see the original (parent, term) state, which is valid.
// ---------------------------------------------------------------------------
__global__ __launch_bounds__(256)
void combined_kernel(const float* __restrict__ diff,
                     const float* __restrict__ attr,
                     const float* __restrict__ weight,
                     const float* __restrict__ bias,
                     const int*   __restrict__ parent,
                     int N,
                     int p1_base, int p1_end, int p1_blocks,
                     int rs_start, int rs_end)
{
    __shared__ float s_attr[768 * 15];
    const int tid = threadIdx.x;

    if ((int)blockIdx.x >= p1_blocks) {
        // ----- resolve role -----
        const int i = rs_start + ((int)blockIdx.x - p1_blocks) * 256 + tid;
        if (i >= rs_end) return;
        const unsigned Nu = (unsigned)N;

        ull cur = __ldg(&g_nodes[i]);
        unsigned p = (unsigned)cur;
        float    t = __uint_as_float((unsigned)(cur >> 32));

        while (p != Nu) {
            const ull m = __ldg(&g_nodes[p]);
            t += __uint_as_float((unsigned)(m >> 32));
            p = (unsigned)m;
        }
        st_cg(&g_nodes[i], pack_node(Nu, t));
        return;
    }

    // ----- phase1 role -----
    const int base = p1_base + (int)blockIdx.x * 768;

    float d[3] = {0.f, 0.f, 0.f};
    int   q[3] = {0, 0, 0};
    #pragma unroll
    for (int k = 0; k < 3; k++) {
        const int i = base + tid + k * 256;
        if (i < p1_end) { d[k] = __ldcs(diff + i); q[k] = __ldcs(parent + i); }
    }

    if (base + 768 <= p1_end) {
        const float4* src = (const float4*)(attr + (size_t)base * 15);
        float4* dst = (float4*)s_attr;
        #pragma unroll
        for (int k = 0; k < 11; k++)
            dst[tid + k * 256] = __ldcs(src + tid + k * 256);
        if (tid < 64) dst[tid + 2816] = __ldcs(src + tid + 2816);
    } else {
        const int rem = (p1_end - base) * 15;
        for (int k = tid; k < rem; k += 256)
            s_attr[k] = __ldcs(attr + (size_t)base * 15 + k);
    }
    __syncthreads();

    float w[17];
    #pragma unroll
    for (int k = 0; k < 17; k++) w[k] = __ldg(weight + k);
    const float b = __ldg(bias);

    #pragma unroll
    for (int k = 0; k < 3; k++) {
        const int i = base + tid + k * 256;
        if (i < p1_end) {
            const float t = d[k] * node_score(s_attr + (tid + k * 256) * 15, w, b);
            g_nodes[i] = pack_node((q[k] < 0) ? (unsigned)N : (unsigned)q[k], t);
        }
    }
}

// ---------------------------------------------------------------------------
// Gather: out[j] = hi32(g_nodes[pn[j]]). 4 pixels/thread; streaming hints
// keep the 128MB pixel traffic from evicting the 16MB g_nodes from L2.
// ---------------------------------------------------------------------------
__global__ __launch_bounds__(256)
void gather_kernel(const int* __restrict__ pn, float* __restrict__ out, int M)
{
    const int j  = blockIdx.x * blockDim.x + threadIdx.x;
    const int i4 = j * 4;
    if (i4 + 3 < M) {
        const int4 p = __ldcs((const int4*)pn + j);
        float4 o;
        o.x = __uint_as_float((unsigned)(__ldg(&g_nodes[p.x]) >> 32));
        o.y = __uint_as_float((unsigned)(__ldg(&g_nodes[p.y]) >> 32));
        o.z = __uint_as_float((unsigned)(__ldg(&g_nodes[p.z]) >> 32));
        o.w = __uint_as_float((unsigned)(__ldg(&g_nodes[p.w]) >> 32));
        __stcs((float4*)out + j, o);
    } else {
        for (int k = i4; k < M; k++)
            out[k] = __uint_as_float((unsigned)(__ldg(&g_nodes[__ldcs(pn + k)]) >> 32));
    }
}

static inline int round768(int x) { return ((x + 767) / 768) * 768; }

extern "C" void kernel_launch(void* const* d_in, const int* in_sizes, int n_in,
                              void* d_out, int out_size)
{
    const float* diff   = (const float*)d_in[0];
    const float* attr   = (const float*)d_in[1];
    const float* weight = (const float*)d_in[2];
    const float* bias   = (const float*)d_in[3];
    const int*   parent = (const int*)d_in[4];
    const int*   pn     = (const int*)d_in[5];
    float*       out    = (float*)d_out;

    const int N = in_sizes[0];
    const int M = out_size;

    // Chunk boundaries (768-aligned; ~N/64, ~N/8, ~N/2).
    int c1 = round768(N >> 6); if (c1 > N) c1 = N;
    int c2 = round768(N >> 3); if (c2 > N) c2 = N; if (c2 < c1) c2 = c1;
    int c3 = round768(N >> 1); if (c3 > N) c3 = N; if (c3 < c2) c3 = c2;

    // K1: phase1 [0, c1)
    {
        const int pb = (c1 + 767) / 768;
        if (pb > 0)
            combined_kernel<<<pb, 256>>>(diff, attr, weight, bias, parent, N,
                                         0, c1, pb, 0, 0);
    }
    // K2: phase1 [c1, c2) + resolve [0, c1)
    {
        const int pb = (c2 - c1 + 767) / 768;
        const int rb = (c1 + 255) / 256;
        if (pb + rb > 0)
            combined_kernel<<<pb + rb, 256>>>(diff, attr, weight, bias, parent, N,
                                              c1, c2, pb, 0, c1);
    }
    // K3: phase1 [c2, c3) + resolve [c1, c2)
    {
        const int pb = (c3 - c2 + 767) / 768;
        const int rb = (c2 - c1 + 255) / 256;
        if (pb + rb > 0)
            combined_kernel<<<pb + rb, 256>>>(diff, attr, weight, bias, parent, N,
                                              c2, c3, pb, c1, c2);
    }
    // K4: phase1 [c3, N) + resolve [c2, c3)
    {
        const int pb = (N - c3 + 767) / 768;
        const int rb = (c3 - c2 + 255) / 256;
        if (pb + rb > 0)
            combined_kernel<<<pb + rb, 256>>>(diff, attr, weight, bias, parent, N,
                                              c3, N, pb, c2, c3);
    }
    // K5: resolve [c3, N)
    {
        const int rb = (N - c3 + 255) / 256;
        if (rb > 0)
            combined_kernel<<<rb, 256>>>(diff, attr, weight, bias, parent, N,
                                         0, 0, 0, c3, N);
    }

    const int gthreads = (M + 3) / 4;
    gather_kernel<<<(gthreads + 255) / 256, 256>>>(pn, out, M);
}

// round 11
// speedup vs baseline: 1.0853x; 1.0853x over previous
#include <cuda_runtime.h>
#include <cstdint>

typedef unsigned long long ull;

#define MAXN (1 << 21)
#define LN2F 0.69314718055994530942f

// g_nodes[i] packs {p : lo 32, sum : hi 32} in one 8B word. Final state:
// p == N, hi = full path sum. Gather reads the hi word.
__device__ ull g_nodes[MAXN];

__device__ __forceinline__ ull pack_node(unsigned p, float t) {
    return ((ull)__float_as_uint(t) << 32) | (ull)p;
}
__device__ __forceinline__ void st_cg(ull* a, ull v) {
    asm volatile("st.relaxed.gpu.b64 [%0], %1;" :: "l"(a), "l"(v) : "memory");
}

// MUFU-lean scoring: 9 lg2 (ln2 folded into weights), lshape = exp2(0.5(L7-L6))
// reusing the logs (replaces 2 sqrt + 1 div), sigmoid = ex2 + rcp, sincos.
__device__ __forceinline__ float node_score(const float* f, const float* w, float b)
{
    float z = b;
    z += w[0] * f[0] + w[1] * f[1] + w[2] * f[2] + w[3] * f[3] + w[4] * f[4];

    float L[9];
    #pragma unroll
    for (int j = 0; j < 9; j++)
        L[j] = __log2f(fabsf(f[6 + j]) + 1e-10f);
    #pragma unroll
    for (int j = 0; j < 9; j++)
        z += (w[5 + j] * LN2F) * L[j];

    // lshape = sqrt(f7)/(sqrt(f6)+1e-10) ; f6,f7 >= 0.1 so eps is negligible
    z += w[14] * exp2f(0.5f * (L[1] - L[0]));

    float sn, cs;
    __sincosf(f[5], &sn, &cs);
    z += w[15] * cs + w[16] * sn;

    return 1.0f / (1.0f + __expf(-z));
}

// ---------------------------------------------------------------------------
// Phase1 body: one 256-node tile staged through 15KB SMEM (fully-coalesced
// float4 stream), one node/thread. MUFU-bound (~14 MUFU instrs/node).
// ---------------------------------------------------------------------------
__device__ __forceinline__ void phase1_body(float* s_attr,
                                            const float* __restrict__ diff,
                                            const float* __restrict__ attr,
                                            const float* __restrict__ weight,
                                            const float* __restrict__ bias,
                                            const int*   __restrict__ parent,
                                            int base, int p1_end, int N)
{
    const int tid = threadIdx.x;
    const int i   = base + tid;

    float d_pref = 0.0f;
    int   q_pref = 0;
    if (i < p1_end) { d_pref = __ldcs(diff + i); q_pref = __ldcs(parent + i); }

    if (base + 256 <= p1_end) {
        const float4* src = (const float4*)(attr + (size_t)base * 15);
        float4* dst = (float4*)s_attr;
        dst[tid]       = __ldcs(src + tid);
        dst[tid + 256] = __ldcs(src + tid + 256);
        dst[tid + 512] = __ldcs(src + tid + 512);
        if (tid < 192) dst[tid + 768] = __ldcs(src + tid + 768);
    } else {
        const int rem = (p1_end - base) * 15;
        for (int k = tid; k < rem; k += 256)
            s_attr[k] = __ldcs(attr + (size_t)base * 15 + k);
    }
    __syncthreads();

    if (i >= p1_end) return;

    float w[17];
    #pragma unroll
    for (int k = 0; k < 17; k++) w[k] = __ldg(weight + k);
    const float b = __ldg(bias);

    const float t = d_pref * node_score(s_attr + tid * 15, w, b);
    g_nodes[i] = pack_node((q_pref < 0) ? (unsigned)N : (unsigned)q_pref, t);
}

// ---------------------------------------------------------------------------
// Resolve body: 1 thread/node pointer chase, read-only, single final publish.
// Invariant: g_nodes[0, rs_end) written by PRIOR kernels; parent < node =>
// termination; racy reads see valid (ancestor, partial) states.
// ---------------------------------------------------------------------------
__device__ __forceinline__ void resolve_body(int i, int rs_end, int N)
{
    if (i >= rs_end) return;
    const unsigned Nu = (unsigned)N;

    ull cur = __ldg(&g_nodes[i]);
    unsigned p = (unsigned)cur;
    float    t = __uint_as_float((unsigned)(cur >> 32));

    while (p != Nu) {
        const ull m = __ldg(&g_nodes[p]);
        t += __uint_as_float((unsigned)(m >> 32));
        p = (unsigned)m;
    }
    st_cg(&g_nodes[i], pack_node(Nu, t));
}

// ---------------------------------------------------------------------------
// Combined kernel: rb resolve blocks Bresenham-interleaved among pb phase1
// blocks so both roles co-occupy every SM. Phase1 is MUFU-bound, resolve is
// l1tex/latency-bound -> disjoint pipes, resolve rides free.
// ---------------------------------------------------------------------------
__global__ __launch_bounds__(256)
void combined_kernel(const float* __restrict__ diff,
                     const float* __restrict__ attr,
                     const float* __restrict__ weight,
                     const float* __restrict__ bias,
                     const int*   __restrict__ parent,
                     int N,
                     int p1_base, int p1_end,
                     int rs_start, int rs_end,
                     int pb, int rb)
{
    __shared__ float s_attr[256 * 15];
    const int bid   = (int)blockIdx.x;
    const int total = pb + rb;

    const long long rb64 = rb;
    const int r_before = (int)((rb64 * bid) / total);
    const int r_after  = (int)((rb64 * (bid + 1)) / total);

    if (r_after > r_before) {
        // resolve role
        resolve_body(rs_start + r_before * 256 + (int)threadIdx.x, rs_end, N);
    } else {
        // phase1 role
        const int p_idx = bid - r_before;
        phase1_body(s_attr, diff, attr, weight, bias, parent,
                    p1_base + p_idx * 256, p1_end, N);
    }
}

// ---------------------------------------------------------------------------
// Gather: out[j] = hi32(g_nodes[pn[j]]). 4 pixels/thread; streaming hints
// keep the 128MB pixel traffic from evicting the 16MB g_nodes from L2.
// ---------------------------------------------------------------------------
__global__ __launch_bounds__(256)
void gather_kernel(const int* __restrict__ pn, float* __restrict__ out, int M)
{
    const int j  = blockIdx.x * blockDim.x + threadIdx.x;
    const int i4 = j * 4;
    if (i4 + 3 < M) {
        const int4 p = __ldcs((const int4*)pn + j);
        float4 o;
        o.x = __uint_as_float((unsigned)(__ldg(&g_nodes[p.x]) >> 32));
        o.y = __uint_as_float((unsigned)(__ldg(&g_nodes[p.y]) >> 32));
        o.z = __uint_as_float((unsigned)(__ldg(&g_nodes[p.z]) >> 32));
        o.w = __uint_as_float((unsigned)(__ldg(&g_nodes[p.w]) >> 32));
        __stcs((float4*)out + j, o);
    } else {
        for (int k = i4; k < M; k++)
            out[k] = __uint_as_float((unsigned)(__ldg(&g_nodes[__ldcs(pn + k)]) >> 32));
    }
}

static inline int round256(int x) { return ((x + 255) / 256) * 256; }

extern "C" void kernel_launch(void* const* d_in, const int* in_sizes, int n_in,
                              void* d_out, int out_size)
{
    const float* diff   = (const float*)d_in[0];
    const float* attr   = (const float*)d_in[1];
    const float* weight = (const float*)d_in[2];
    const float* bias   = (const float*)d_in[3];
    const int*   parent = (const int*)d_in[4];
    const int*   pn     = (const int*)d_in[5];
    float*       out    = (float*)d_out;

    const int N = in_sizes[0];
    const int M = out_size;

    // Chunk boundaries (256-aligned): c1 ~ N/16, c2 ~ N/2.
    int c1 = round256(N >> 4); if (c1 > N) c1 = N;
    int c2 = round256(N >> 1); if (c2 > N) c2 = N; if (c2 < c1) c2 = c1;

    // K1: phase1 [0, c1)
    {
        const int pb = (c1 + 255) / 256;
        if (pb > 0)
            combined_kernel<<<pb, 256>>>(diff, attr, weight, bias, parent, N,
                                         0, c1, 0, 0, pb, 0);
    }
    // K2: phase1 [c1, c2) + resolve [0, c1)
    {
        const int pb = (c2 - c1 + 255) / 256;
        const int rb = (c1 + 255) / 256;
        if (pb + rb > 0)
            combined_kernel<<<pb + rb, 256>>>(diff, attr, weight, bias, parent, N,
                                              c1, c2, 0, c1, pb, rb);
    }
    // K3: phase1 [c2, N) + resolve [c1, c2)
    {
        const int pb = (N - c2 + 255) / 256;
        const int rb = (c2 - c1 + 255) / 256;
        if (pb + rb > 0)
            combined_kernel<<<pb + rb, 256>>>(diff, attr, weight, bias, parent, N,
                                              c2, N, c1, c2, pb, rb);
    }
    // K4: resolve [c2, N)
    {
        const int rb = (N - c2 + 255) / 256;
        if (rb > 0)
            combined_kernel<<<rb, 256>>>(diff, attr, weight, bias, parent, N,
                                         0, 0, c2, N, 0, rb);
    }

    const int gthreads = (M + 3) / 4;
    gather_kernel<<<(gthreads + 255) / 256, 256>>>(pn, out, M);
}

// round 12
// speedup vs baseline: 1.1107x; 1.0234x over previous
#include <cuda_runtime.h>
#include <cstdint>

typedef unsigned long long ull;

#define MAXN (1 << 21)
#define LN2F 0.69314718055994530942f

// g_nodes[i] packs {p : lo 32, sum : hi 32} in one 8B word. Final state:
// p == N, hi = full path sum.
__device__ ull g_nodes[MAXN];

__device__ __forceinline__ ull pack_node(unsigned p, float t) {
    return ((ull)__float_as_uint(t) << 32) | (ull)p;
}
__device__ __forceinline__ void st_cg(ull* a, ull v) {
    asm volatile("st.relaxed.gpu.b64 [%0], %1;" :: "l"(a), "l"(v) : "memory");
}

// MUFU-lean scoring: 9 lg2 (ln2 folded into weights), lshape = exp2(0.5(L7-L6))
// reusing the logs, sigmoid = ex2 + rcp, sincos.
__device__ __forceinline__ float node_score(const float* f, const float* w, float b)
{
    float z = b;
    z += w[0] * f[0] + w[1] * f[1] + w[2] * f[2] + w[3] * f[3] + w[4] * f[4];

    float L[9];
    #pragma unroll
    for (int j = 0; j < 9; j++)
        L[j] = __log2f(fabsf(f[6 + j]) + 1e-10f);
    #pragma unroll
    for (int j = 0; j < 9; j++)
        z += (w[5 + j] * LN2F) * L[j];

    z += w[14] * exp2f(0.5f * (L[1] - L[0]));

    float sn, cs;
    __sincosf(f[5], &sn, &cs);
    z += w[15] * cs + w[16] * sn;

    return 1.0f / (1.0f + __expf(-z));
}

__device__ __forceinline__ void phase1_body(float* s_attr,
                                            const float* __restrict__ diff,
                                            const float* __restrict__ attr,
                                            const float* __restrict__ weight,
                                            const float* __restrict__ bias,
                                            const int*   __restrict__ parent,
                                            int base, int p1_end, int N)
{
    const int tid = threadIdx.x;
    const int i   = base + tid;

    float d_pref = 0.0f;
    int   q_pref = 0;
    if (i < p1_end) { d_pref = __ldcs(diff + i); q_pref = __ldcs(parent + i); }

    if (base + 256 <= p1_end) {
        const float4* src = (const float4*)(attr + (size_t)base * 15);
        float4* dst = (float4*)s_attr;
        dst[tid]       = __ldcs(src + tid);
        dst[tid + 256] = __ldcs(src + tid + 256);
        dst[tid + 512] = __ldcs(src + tid + 512);
        if (tid < 192) dst[tid + 768] = __ldcs(src + tid + 768);
    } else {
        const int rem = (p1_end - base) * 15;
        for (int k = tid; k < rem; k += 256)
            s_attr[k] = __ldcs(attr + (size_t)base * 15 + k);
    }
    __syncthreads();

    if (i >= p1_end) return;

    float w[17];
    #pragma unroll
    for (int k = 0; k < 17; k++) w[k] = __ldg(weight + k);
    const float b = __ldg(bias);

    const float t = d_pref * node_score(s_attr + tid * 15, w, b);
    g_nodes[i] = pack_node((q_pref < 0) ? (unsigned)N : (unsigned)q_pref, t);
}

__device__ __forceinline__ void resolve_body(int i, int rs_end, int N)
{
    if (i >= rs_end) return;
    const unsigned Nu = (unsigned)N;

    ull cur = __ldg(&g_nodes[i]);
    unsigned p = (unsigned)cur;
    float    t = __uint_as_float((unsigned)(cur >> 32));

    while (p != Nu) {
        const ull m = __ldg(&g_nodes[p]);
        t += __uint_as_float((unsigned)(m >> 32));
        p = (unsigned)m;
    }
    st_cg(&g_nodes[i], pack_node(Nu, t));
}

// ---------------------------------------------------------------------------
// Combined phase1+resolve kernel (Bresenham-interleaved roles). Phase1 is
// MUFU/DRAM-bound, resolve is l1tex/latency-bound -> resolve rides free.
// ---------------------------------------------------------------------------
__global__ __launch_bounds__(256)
void combined_kernel(const float* __restrict__ diff,
                     const float* __restrict__ attr,
                     const float* __restrict__ weight,
                     const float* __restrict__ bias,
                     const int*   __restrict__ parent,
                     int N,
                     int p1_base, int p1_end,
                     int rs_start, int rs_end,
                     int pb, int rb)
{
    __shared__ float s_attr[256 * 15];
    const int bid   = (int)blockIdx.x;
    const int total = pb + rb;

    const long long rb64 = rb;
    const int r_before = (int)((rb64 * bid) / total);
    const int r_after  = (int)((rb64 * (bid + 1)) / total);

    if (r_after > r_before) {
        resolve_body(rs_start + r_before * 256 + (int)threadIdx.x, rs_end, N);
    } else {
        const int p_idx = bid - r_before;
        phase1_body(s_attr, diff, attr, weight, bias, parent,
                    p1_base + p_idx * 256, p1_end, N);
    }
}

// ---------------------------------------------------------------------------
// Dual-role final kernel: blocks [0, rb) resolve the last slab [rs_start, N)
// (scheduled first, done in ~8us); the remaining blocks gather 4 px/thread
// with a chase-on-demand fallback for nodes the resolvers haven't finished
// yet (all ancestors < rs_start are final; expected 1.39 hops; chased sums
// are bit-identical to resolved ones since path order is fixed). This hides
// the last resolve slab's wall time inside the gather.
// ---------------------------------------------------------------------------
__global__ __launch_bounds__(256)
void gather_resolve_kernel(const int* __restrict__ pn, float* __restrict__ out,
                           int M, int N, int rs_start, int rb)
{
    const unsigned Nu = (unsigned)N;
    const int bid = (int)blockIdx.x;
    const int tid = (int)threadIdx.x;

    if (bid < rb) {
        resolve_body(rs_start + bid * 256 + tid, N, N);
        return;
    }

    const int j  = (bid - rb) * 256 + tid;
    const int i4 = j * 4;

    if (i4 + 3 < M) {
        const int4 pv = __ldcs((const int4*)pn + j);
        int idx[4] = {pv.x, pv.y, pv.z, pv.w};

        ull m[4];
        #pragma unroll
        for (int k = 0; k < 4; k++) m[k] = __ldg(&g_nodes[idx[k]]);

        float o[4];
        #pragma unroll
        for (int k = 0; k < 4; k++) {
            unsigned p = (unsigned)m[k];
            float    s = __uint_as_float((unsigned)(m[k] >> 32));
            if (p != Nu) {                       // rare after ~15% of kernel
                do {
                    const ull mm = __ldg(&g_nodes[p]);
                    s += __uint_as_float((unsigned)(mm >> 32));
                    p = (unsigned)mm;
                } while (p != Nu);
                st_cg(&g_nodes[idx[k]], pack_node(Nu, s));  // help later touchers
            }
            o[k] = s;
        }

        float4 ov = {o[0], o[1], o[2], o[3]};
        __stcs((float4*)out + j, ov);
    } else {
        for (int k = i4; k < M; k++) {
            const int idx = __ldcs(pn + k);
            ull cur = __ldg(&g_nodes[idx]);
            unsigned p = (unsigned)cur;
            float    s = __uint_as_float((unsigned)(cur >> 32));
            while (p != Nu) {
                const ull mm = __ldg(&g_nodes[p]);
                s += __uint_as_float((unsigned)(mm >> 32));
                p = (unsigned)mm;
            }
            out[k] = s;
        }
    }
}

static inline int round256(int x) { return ((x + 255) / 256) * 256; }

extern "C" void kernel_launch(void* const* d_in, const int* in_sizes, int n_in,
                              void* d_out, int out_size)
{
    const float* diff   = (const float*)d_in[0];
    const float* attr   = (const float*)d_in[1];
    const float* weight = (const float*)d_in[2];
    const float* bias   = (const float*)d_in[3];
    const int*   parent = (const int*)d_in[4];
    const int*   pn     = (const int*)d_in[5];
    float*       out    = (float*)d_out;

    const int N = in_sizes[0];
    const int M = out_size;

    int c1 = round256(N >> 4); if (c1 > N) c1 = N;
    int c2 = round256(N >> 1); if (c2 > N) c2 = N; if (c2 < c1) c2 = c1;

    // K1: phase1 [0, c1)
    {
        const int pb = (c1 + 255) / 256;
        if (pb > 0)
            combined_kernel<<<pb, 256>>>(diff, attr, weight, bias, parent, N,
                                         0, c1, 0, 0, pb, 0);
    }
    // K2: phase1 [c1, c2) + resolve [0, c1)
    {
        const int pb = (c2 - c1 + 255) / 256;
        const int rb = (c1 + 255) / 256;
        if (pb + rb > 0)
            combined_kernel<<<pb + rb, 256>>>(diff, attr, weight, bias, parent, N,
                                              c1, c2, 0, c1, pb, rb);
    }
    // K3: phase1 [c2, N) + resolve [c1, c2)
    {
        const int pb = (N - c2 + 255) / 256;
        const int rb = (c2 - c1 + 255) / 256;
        if (pb + rb > 0)
            combined_kernel<<<pb + rb, 256>>>(diff, attr, weight, bias, parent, N,
                                              c2, N, c1, c2, pb, rb);
    }
    // K4: resolve [c2, N) fused into the gather (resolve blocks first).
    {
        const int rb = (N - c2 + 255) / 256;
        const int gb = ((M + 3) / 4 + 255) / 256;
        gather_resolve_kernel<<<rb + gb, 256>>>(pn, out, M, N, c2, rb);
    }
}